// round 1
// baseline (speedup 1.0000x reference)
#include <cuda_runtime.h>
#include <math.h>
#include <stdint.h>

#define N_NODES  50000
#define N_EDGES  800000
#define FEAT     90
#define H        128
#define STEPS    4
#define N_GRAPHS 100
#define M_PAD    50048   // 128 * 391

// ---------------- device scratch (static allocation is allowed) ----------------
__device__ float g_h  [(size_t)M_PAD * H];
__device__ float g_m  [(size_t)M_PAD * H];
__device__ float g_agg[(size_t)M_PAD * H];
__device__ float g_gx [(size_t)M_PAD * 3 * H];
__device__ float g_gh [(size_t)M_PAD * 3 * H];
__device__ float g_pool[N_GRAPHS * H];
__device__ float g_cnt [N_GRAPHS];

// ---------------- embedding: h = relu(x @ W_emb), K=90 ----------------
// block: 128 threads (one output column each), 32 nodes per block.
__global__ void embed_kernel(const float* __restrict__ x,
                             const float* __restrict__ Wemb) {
    extern __shared__ float sm[];
    float* Ws = sm;               // FEAT*H
    float* xs = sm + FEAT * H;    // 32*FEAT
    const int tid = threadIdx.x;
    for (int i = tid; i < FEAT * H; i += 128) Ws[i] = Wemb[i];
    const int n0 = blockIdx.x * 32;
    for (int i = tid; i < 32 * FEAT; i += 128) {
        int r = i / FEAT, cc = i - r * FEAT;
        int n = n0 + r;
        xs[i] = (n < N_NODES) ? x[(size_t)n * FEAT + cc] : 0.f;
    }
    __syncthreads();
    const int c = tid;
    for (int r = 0; r < 32; r++) {
        float acc = 0.f;
        const float* xr = xs + r * FEAT;
        #pragma unroll 6
        for (int k = 0; k < FEAT; k++) acc = fmaf(xr[k], Ws[k * H + c], acc);
        g_h[(size_t)(n0 + r) * H + c] = fmaxf(acc, 0.f);
    }
}

// ---------------- generic GEMM: C[M_PAD,N] = A[M_PAD,128] @ W[128,N] (+bias) ----
// BM=128, BN=64, BK=8, 256 threads, 8x4 register tile per thread.
template<bool BIAS>
__global__ void __launch_bounds__(256) gemm_k128(
        const float* __restrict__ A, const float* __restrict__ W,
        const float* __restrict__ bias, float* __restrict__ C, int N) {
    __shared__ float As[8][128];
    __shared__ float Bs[8][64];
    const int tid = threadIdx.x;
    const int m0 = blockIdx.y * 128;
    const int n0 = blockIdx.x * 64;
    const int ty = tid >> 4;          // 0..15 -> 8 rows each
    const int tx = tid & 15;          // 0..15 -> 4 cols each
    const int arow = tid >> 1;        // A load: row 0..127
    const int ak   = (tid & 1) << 2;  // k offset 0 or 4
    const int bk   = tid >> 5;        // B load: k row 0..7
    const int bn   = (tid & 31) << 1; // col pair
    const float* Ap = A + (size_t)(m0 + arow) * H + ak;
    const float* Wp = W + (size_t)bk * N + n0 + bn;

    float acc[8][4];
    #pragma unroll
    for (int i = 0; i < 8; i++)
        #pragma unroll
        for (int j = 0; j < 4; j++) acc[i][j] = 0.f;

    for (int k0 = 0; k0 < 128; k0 += 8) {
        float4 av = *(const float4*)(Ap + k0);
        float2 bv = *(const float2*)(Wp + (size_t)k0 * N);
        __syncthreads();
        As[ak + 0][arow] = av.x;
        As[ak + 1][arow] = av.y;
        As[ak + 2][arow] = av.z;
        As[ak + 3][arow] = av.w;
        Bs[bk][bn]     = bv.x;
        Bs[bk][bn + 1] = bv.y;
        __syncthreads();
        #pragma unroll
        for (int kk = 0; kk < 8; kk++) {
            float a[8], b[4];
            *(float4*)(a)     = *(const float4*)(&As[kk][ty * 8]);
            *(float4*)(a + 4) = *(const float4*)(&As[kk][ty * 8 + 4]);
            *(float4*)(b)     = *(const float4*)(&Bs[kk][tx * 4]);
            #pragma unroll
            for (int i = 0; i < 8; i++)
                #pragma unroll
                for (int j = 0; j < 4; j++)
                    acc[i][j] = fmaf(a[i], b[j], acc[i][j]);
        }
    }

    float4 bb = make_float4(0.f, 0.f, 0.f, 0.f);
    if (BIAS) bb = *(const float4*)(bias + n0 + tx * 4);
    #pragma unroll
    for (int i = 0; i < 8; i++) {
        int row = m0 + ty * 8 + i;
        float4 o;
        o.x = acc[i][0] + bb.x;
        o.y = acc[i][1] + bb.y;
        o.z = acc[i][2] + bb.z;
        o.w = acc[i][3] + bb.w;
        *(float4*)(C + (size_t)row * N + n0 + tx * 4) = o;
    }
}

// ---------------- edge scatter: agg[dst] += m[src], one warp per edge --------
__global__ void scatter_kernel(const int* __restrict__ ei) {
    const int gw = (blockIdx.x * blockDim.x + threadIdx.x) >> 5;
    const int lane = threadIdx.x & 31;
    const int src = ei[gw];
    const int dst = ei[N_EDGES + gw];
    float4 v = *((const float4*)(g_m + (size_t)src * H) + lane);
    float* p = g_agg + (size_t)dst * H + lane * 4;
    asm volatile("red.global.add.v4.f32 [%0], {%1,%2,%3,%4};"
                 :: "l"(p), "f"(v.x), "f"(v.y), "f"(v.z), "f"(v.w)
                 : "memory");
}

// ---------------- GRU elementwise: h = gru(gx, gh, h) ------------------------
__device__ __forceinline__ float sigmoidf_(float x) { return 1.f / (1.f + expf(-x)); }

__global__ void gru_kernel() {
    size_t i = (size_t)blockIdx.x * blockDim.x + threadIdx.x; // < M_PAD*H exact
    int n = (int)(i >> 7), c = (int)(i & 127);
    size_t b = (size_t)n * 384 + c;
    float xr = g_gx[b], xz = g_gx[b + 128], xn = g_gx[b + 256];
    float hr = g_gh[b], hz = g_gh[b + 128], hn = g_gh[b + 256];
    float hv = g_h[i];
    float r = sigmoidf_(xr + hr);
    float z = sigmoidf_(xz + hz);
    float nn = tanhf(xn + r * hn);
    g_h[i] = (1.f - z) * nn + z * hv;
}

// ---------------- pooling: sum relu(h) per graph (batch sorted) --------------
__global__ void pool_kernel(const int* __restrict__ batch) {
    __shared__ int bs[256];
    const int tid = threadIdx.x;        // 128 threads, one column each
    const int n0 = blockIdx.x * 256;
    const int cnt = min(256, N_NODES - n0);
    for (int i = tid; i < cnt; i += 128) bs[i] = batch[n0 + i];
    __syncthreads();
    const int c = tid;
    float sum = 0.f;
    int cur = bs[0];
    int run = 0;
    for (int i = 0; i < cnt; i++) {
        int b = bs[i];
        if (b != cur) {
            atomicAdd(&g_pool[cur * H + c], sum);
            if (c == 0) atomicAdd(&g_cnt[cur], (float)run);
            sum = 0.f; run = 0; cur = b;
        }
        sum += fmaxf(g_h[(size_t)(n0 + i) * H + c], 0.f);
        run++;
    }
    atomicAdd(&g_pool[cur * H + c], sum);
    if (c == 0) atomicAdd(&g_cnt[cur], (float)run);
}

// ---------------- head: mean -> Linear+ReLU -> Linear -> softplus ------------
__global__ void head_kernel(const float* __restrict__ W1, const float* __restrict__ b1,
                            const float* __restrict__ W2, const float* __restrict__ b2,
                            float* __restrict__ out) {
    __shared__ float ps[H];
    __shared__ float hs[H];
    const int g = blockIdx.x, c = threadIdx.x;
    float cnt = fmaxf(g_cnt[g], 1.f);
    ps[c] = g_pool[g * H + c] / cnt;
    __syncthreads();
    float acc = b1[c];
    #pragma unroll 8
    for (int k = 0; k < H; k++) acc = fmaf(ps[k], W1[k * H + c], acc);
    hs[c] = fmaxf(acc, 0.f) * W2[c];
    __syncthreads();
    for (int s = 64; s > 0; s >>= 1) {
        if (c < s) hs[c] += hs[c + s];
        __syncthreads();
    }
    if (c == 0) {
        float xv = hs[0] + b2[0];
        out[g] = (xv > 0.f) ? (xv + log1pf(expf(-xv))) : log1pf(expf(xv));
    }
}

// ---------------- launch ------------------------------------------------------
extern "C" void kernel_launch(void* const* d_in, const int* in_sizes, int n_in,
                              void* d_out, int out_size) {
    const float* x     = (const float*)d_in[0];
    const int*   ei    = (const int*)d_in[1];
    const int*   batch = (const int*)d_in[2];
    const float* W_emb = (const float*)d_in[3];
    const float* W_msg = (const float*)d_in[4];
    const float* W_ih  = (const float*)d_in[5];
    const float* W_hh  = (const float*)d_in[6];
    const float* b_ih  = (const float*)d_in[7];
    const float* b_hh  = (const float*)d_in[8];
    const float* W1    = (const float*)d_in[9];
    const float* b1    = (const float*)d_in[10];
    const float* W2    = (const float*)d_in[11];
    const float* b2    = (const float*)d_in[12];
    float* out = (float*)d_out;

    float *h_p, *m_p, *agg_p, *gx_p, *gh_p, *pool_p, *cnt_p;
    cudaGetSymbolAddress((void**)&h_p,   g_h);
    cudaGetSymbolAddress((void**)&m_p,   g_m);
    cudaGetSymbolAddress((void**)&agg_p, g_agg);
    cudaGetSymbolAddress((void**)&gx_p,  g_gx);
    cudaGetSymbolAddress((void**)&gh_p,  g_gh);
    cudaGetSymbolAddress((void**)&pool_p, g_pool);
    cudaGetSymbolAddress((void**)&cnt_p,  g_cnt);

    const int embed_smem = (FEAT * H + 32 * FEAT) * 4;  // 57600 B
    cudaFuncSetAttribute(embed_kernel,
                         cudaFuncAttributeMaxDynamicSharedMemorySize, embed_smem);

    // 1) embed
    embed_kernel<<<M_PAD / 32, 128, embed_smem>>>(x, W_emb);

    // 2) message-passing steps
    for (int s = 0; s < STEPS; s++) {
        gemm_k128<false><<<dim3(H / 64, M_PAD / 128), 256>>>(
            h_p, W_msg + (size_t)s * H * H, nullptr, m_p, H);
        cudaMemsetAsync(agg_p, 0, (size_t)M_PAD * H * sizeof(float));
        scatter_kernel<<<(N_EDGES * 32) / 256, 256>>>(ei);
        gemm_k128<true><<<dim3(3 * H / 64, M_PAD / 128), 256>>>(
            agg_p, W_ih, b_ih, gx_p, 3 * H);
        gemm_k128<true><<<dim3(3 * H / 64, M_PAD / 128), 256>>>(
            h_p, W_hh, b_hh, gh_p, 3 * H);
        gru_kernel<<<(M_PAD * H) / 256, 256>>>();
    }

    // 3) pooling
    cudaMemsetAsync(pool_p, 0, N_GRAPHS * H * sizeof(float));
    cudaMemsetAsync(cnt_p, 0, N_GRAPHS * sizeof(float));
    pool_kernel<<<(N_NODES + 255) / 256, 128>>>(batch);

    // 4) head
    head_kernel<<<N_GRAPHS, H>>>(W1, b1, W2, b2, out);
}

// round 2
// speedup vs baseline: 1.0664x; 1.0664x over previous
#include <cuda_runtime.h>
#include <math.h>
#include <stdint.h>

#define N_NODES  50000
#define N_EDGES  800000
#define FEAT     90
#define H        128
#define STEPS    4
#define N_GRAPHS 100
#define M_PAD    50048   // 128 * 391

typedef unsigned long long u64;

// ---------------- device scratch ----------------
__device__ float g_h  [(size_t)M_PAD * H];
__device__ float g_m  [(size_t)M_PAD * H];
__device__ float g_agg[(size_t)M_PAD * H];
__device__ float g_gx [(size_t)M_PAD * 3 * H];
__device__ float g_gh [(size_t)M_PAD * 3 * H];
__device__ float g_pool[N_GRAPHS * H];
__device__ float g_cnt [N_GRAPHS];

// ---------------- packed f32x2 helpers ----------------
__device__ __forceinline__ void fma2(u64& d, u64 a, u64 b) {
    asm("fma.rn.f32x2 %0, %1, %2, %0;" : "+l"(d) : "l"(a), "l"(b));
}
__device__ __forceinline__ u64 pack2(float x) {
    u64 r; asm("mov.b64 %0, {%1, %1};" : "=l"(r) : "f"(x)); return r;
}
__device__ __forceinline__ float2 unpack2(u64 v) {
    float2 r; asm("mov.b64 {%0, %1}, %2;" : "=f"(r.x), "=f"(r.y) : "l"(v)); return r;
}

// ---------------- embedding: h = relu(x @ W_emb), K=90 ----------------
__global__ void embed_kernel(const float* __restrict__ x,
                             const float* __restrict__ Wemb) {
    extern __shared__ float sm[];
    float* Ws = sm;               // FEAT*H
    float* xs = sm + FEAT * H;    // 32*FEAT
    const int tid = threadIdx.x;
    for (int i = tid; i < FEAT * H; i += 128) Ws[i] = Wemb[i];
    const int n0 = blockIdx.x * 32;
    for (int i = tid; i < 32 * FEAT; i += 128) {
        int r = i / FEAT, cc = i - r * FEAT;
        int n = n0 + r;
        xs[i] = (n < N_NODES) ? x[(size_t)n * FEAT + cc] : 0.f;
    }
    __syncthreads();
    const int c = tid;
    for (int r = 0; r < 32; r++) {
        float acc = 0.f;
        const float* xr = xs + r * FEAT;
        #pragma unroll 6
        for (int k = 0; k < FEAT; k++) acc = fmaf(xr[k], Ws[k * H + c], acc);
        g_h[(size_t)(n0 + r) * H + c] = fmaxf(acc, 0.f);
    }
}

// ---------------- GEMM: C[M_PAD,N] = A[M_PAD,128] @ W[128,N] (+bias) ----------
// BM=128, BN=128, BK=16, 256 threads, 8x8 thread tile, fma.rn.f32x2,
// double-buffered shared memory.
template<bool BIAS>
__global__ void __launch_bounds__(256) gemm_f2(
        const float* __restrict__ A, const float* __restrict__ W,
        const float* __restrict__ bias, float* __restrict__ C, int N) {
    __shared__ float As[2][16][132];   // [k][m], padded stride
    __shared__ float Bs[2][16][128];   // [k][n]

    const int tid = threadIdx.x;
    const int m0 = blockIdx.y * 128;
    const int n0 = blockIdx.x * 128;
    const int ty = tid >> 4;           // 0..15 -> rows ty*8..+7
    const int tx = tid & 15;           // 0..15 -> cols tx*8..+7

    // A tile load mapping: thread -> (row, k-offset)
    const int ar = tid >> 1;           // 0..127
    const int ak = (tid & 1) * 8;      // 0 or 8
    // B tile load mapping: thread -> (k-row, col4)
    const int bk = tid >> 4;           // 0..15
    const int bn = (tid & 15) * 4;     // 0..60

    const float* Ap = A + (size_t)(m0 + ar) * 128 + ak;
    const float* Wp = W + (size_t)bk * N + n0 + bn;

    u64 acc[8][4];
    #pragma unroll
    for (int i = 0; i < 8; i++)
        #pragma unroll
        for (int j = 0; j < 4; j++) acc[i][j] = 0ULL;

    // prefetch chunk 0
    float4 a0 = *(const float4*)(Ap);
    float4 a1 = *(const float4*)(Ap + 4);
    float4 b0 = *(const float4*)(Wp);
    float4 b1 = *(const float4*)(Wp + 64);

    // store chunk 0 into buffer 0
    As[0][ak + 0][ar] = a0.x; As[0][ak + 1][ar] = a0.y;
    As[0][ak + 2][ar] = a0.z; As[0][ak + 3][ar] = a0.w;
    As[0][ak + 4][ar] = a1.x; As[0][ak + 5][ar] = a1.y;
    As[0][ak + 6][ar] = a1.z; As[0][ak + 7][ar] = a1.w;
    *(float4*)&Bs[0][bk][bn]      = b0;
    *(float4*)&Bs[0][bk][bn + 64] = b1;
    __syncthreads();

    #pragma unroll
    for (int c = 0; c < 8; c++) {
        const int cur = c & 1;
        // prefetch next chunk from gmem
        if (c < 7) {
            a0 = *(const float4*)(Ap + (c + 1) * 16);
            a1 = *(const float4*)(Ap + (c + 1) * 16 + 4);
            b0 = *(const float4*)(Wp + (size_t)(c + 1) * 16 * N);
            b1 = *(const float4*)(Wp + (size_t)(c + 1) * 16 * N + 64);
        }
        // compute current buffer
        #pragma unroll
        for (int kk = 0; kk < 16; kk++) {
            float4 af0 = *(const float4*)&As[cur][kk][ty * 8];
            float4 af1 = *(const float4*)&As[cur][kk][ty * 8 + 4];
            ulonglong2 bu0 = *(const ulonglong2*)&Bs[cur][kk][tx * 8];
            ulonglong2 bu1 = *(const ulonglong2*)&Bs[cur][kk][tx * 8 + 4];
            u64 a2[8];
            a2[0] = pack2(af0.x); a2[1] = pack2(af0.y);
            a2[2] = pack2(af0.z); a2[3] = pack2(af0.w);
            a2[4] = pack2(af1.x); a2[5] = pack2(af1.y);
            a2[6] = pack2(af1.z); a2[7] = pack2(af1.w);
            #pragma unroll
            for (int i = 0; i < 8; i++) {
                fma2(acc[i][0], a2[i], bu0.x);
                fma2(acc[i][1], a2[i], bu0.y);
                fma2(acc[i][2], a2[i], bu1.x);
                fma2(acc[i][3], a2[i], bu1.y);
            }
        }
        // store next chunk into other buffer
        if (c < 7) {
            const int nxt = cur ^ 1;
            __syncthreads();
            As[nxt][ak + 0][ar] = a0.x; As[nxt][ak + 1][ar] = a0.y;
            As[nxt][ak + 2][ar] = a0.z; As[nxt][ak + 3][ar] = a0.w;
            As[nxt][ak + 4][ar] = a1.x; As[nxt][ak + 5][ar] = a1.y;
            As[nxt][ak + 6][ar] = a1.z; As[nxt][ak + 7][ar] = a1.w;
            *(float4*)&Bs[nxt][bk][bn]      = b0;
            *(float4*)&Bs[nxt][bk][bn + 64] = b1;
            __syncthreads();
        }
    }

    // epilogue
    float4 bb0 = make_float4(0.f, 0.f, 0.f, 0.f);
    float4 bb1 = bb0;
    if (BIAS) {
        bb0 = *(const float4*)(bias + n0 + tx * 8);
        bb1 = *(const float4*)(bias + n0 + tx * 8 + 4);
    }
    #pragma unroll
    for (int i = 0; i < 8; i++) {
        int row = m0 + ty * 8 + i;
        float2 p0 = unpack2(acc[i][0]);
        float2 p1 = unpack2(acc[i][1]);
        float2 p2 = unpack2(acc[i][2]);
        float2 p3 = unpack2(acc[i][3]);
        float4 o0 = make_float4(p0.x + bb0.x, p0.y + bb0.y, p1.x + bb0.z, p1.y + bb0.w);
        float4 o1 = make_float4(p2.x + bb1.x, p2.y + bb1.y, p3.x + bb1.z, p3.y + bb1.w);
        float* Cp = C + (size_t)row * N + n0 + tx * 8;
        *(float4*)(Cp)     = o0;
        *(float4*)(Cp + 4) = o1;
    }
}

// ---------------- edge scatter: agg[dst] += m[src], one warp per edge --------
__global__ void scatter_kernel(const int* __restrict__ ei) {
    const int gw = (blockIdx.x * blockDim.x + threadIdx.x) >> 5;
    const int lane = threadIdx.x & 31;
    const int src = ei[gw];
    const int dst = ei[N_EDGES + gw];
    float4 v = *((const float4*)(g_m + (size_t)src * H) + lane);
    float* p = g_agg + (size_t)dst * H + lane * 4;
    asm volatile("red.global.add.v4.f32 [%0], {%1,%2,%3,%4};"
                 :: "l"(p), "f"(v.x), "f"(v.y), "f"(v.z), "f"(v.w)
                 : "memory");
}

// ---------------- GRU elementwise (float4 vectorized) ------------------------
__device__ __forceinline__ float sigmoidf_(float x) { return 1.f / (1.f + expf(-x)); }

__global__ void gru_kernel() {
    const int v = blockIdx.x * blockDim.x + threadIdx.x;  // vec4 index, < M_PAD*32
    const int node = v >> 5;
    const int c4 = (v & 31) * 4;
    const size_t gb = (size_t)node * 384 + c4;
    const size_t hb = (size_t)node * 128 + c4;
    float4 xr = *(const float4*)&g_gx[gb];
    float4 xz = *(const float4*)&g_gx[gb + 128];
    float4 xn = *(const float4*)&g_gx[gb + 256];
    float4 hr = *(const float4*)&g_gh[gb];
    float4 hz = *(const float4*)&g_gh[gb + 128];
    float4 hn = *(const float4*)&g_gh[gb + 256];
    float4 hv = *(const float4*)&g_h[hb];
    float4 o;
    {
        float r = sigmoidf_(xr.x + hr.x), z = sigmoidf_(xz.x + hz.x);
        float nn = tanhf(xn.x + r * hn.x);
        o.x = (1.f - z) * nn + z * hv.x;
    }
    {
        float r = sigmoidf_(xr.y + hr.y), z = sigmoidf_(xz.y + hz.y);
        float nn = tanhf(xn.y + r * hn.y);
        o.y = (1.f - z) * nn + z * hv.y;
    }
    {
        float r = sigmoidf_(xr.z + hr.z), z = sigmoidf_(xz.z + hz.z);
        float nn = tanhf(xn.z + r * hn.z);
        o.z = (1.f - z) * nn + z * hv.z;
    }
    {
        float r = sigmoidf_(xr.w + hr.w), z = sigmoidf_(xz.w + hz.w);
        float nn = tanhf(xn.w + r * hn.w);
        o.w = (1.f - z) * nn + z * hv.w;
    }
    *(float4*)&g_h[hb] = o;
}

// ---------------- pooling: sum relu(h) per graph (batch sorted) --------------
__global__ void pool_kernel(const int* __restrict__ batch) {
    __shared__ int bs[256];
    const int tid = threadIdx.x;        // 128 threads, one column each
    const int n0 = blockIdx.x * 256;
    const int cnt = min(256, N_NODES - n0);
    for (int i = tid; i < cnt; i += 128) bs[i] = batch[n0 + i];
    __syncthreads();
    const int c = tid;
    float sum = 0.f;
    int cur = bs[0];
    int run = 0;
    for (int i = 0; i < cnt; i++) {
        int b = bs[i];
        if (b != cur) {
            atomicAdd(&g_pool[cur * H + c], sum);
            if (c == 0) atomicAdd(&g_cnt[cur], (float)run);
            sum = 0.f; run = 0; cur = b;
        }
        sum += fmaxf(g_h[(size_t)(n0 + i) * H + c], 0.f);
        run++;
    }
    atomicAdd(&g_pool[cur * H + c], sum);
    if (c == 0) atomicAdd(&g_cnt[cur], (float)run);
}

// ---------------- head: mean -> Linear+ReLU -> Linear -> softplus ------------
__global__ void head_kernel(const float* __restrict__ W1, const float* __restrict__ b1,
                            const float* __restrict__ W2, const float* __restrict__ b2,
                            float* __restrict__ out) {
    __shared__ float ps[H];
    __shared__ float hs[H];
    const int g = blockIdx.x, c = threadIdx.x;
    float cnt = fmaxf(g_cnt[g], 1.f);
    ps[c] = g_pool[g * H + c] / cnt;
    __syncthreads();
    float acc = b1[c];
    #pragma unroll 8
    for (int k = 0; k < H; k++) acc = fmaf(ps[k], W1[k * H + c], acc);
    hs[c] = fmaxf(acc, 0.f) * W2[c];
    __syncthreads();
    for (int s = 64; s > 0; s >>= 1) {
        if (c < s) hs[c] += hs[c + s];
        __syncthreads();
    }
    if (c == 0) {
        float xv = hs[0] + b2[0];
        out[g] = (xv > 0.f) ? (xv + log1pf(expf(-xv))) : log1pf(expf(xv));
    }
}

// ---------------- launch ------------------------------------------------------
extern "C" void kernel_launch(void* const* d_in, const int* in_sizes, int n_in,
                              void* d_out, int out_size) {
    const float* x     = (const float*)d_in[0];
    const int*   ei    = (const int*)d_in[1];
    const int*   batch = (const int*)d_in[2];
    const float* W_emb = (const float*)d_in[3];
    const float* W_msg = (const float*)d_in[4];
    const float* W_ih  = (const float*)d_in[5];
    const float* W_hh  = (const float*)d_in[6];
    const float* b_ih  = (const float*)d_in[7];
    const float* b_hh  = (const float*)d_in[8];
    const float* W1    = (const float*)d_in[9];
    const float* b1    = (const float*)d_in[10];
    const float* W2    = (const float*)d_in[11];
    const float* b2    = (const float*)d_in[12];
    float* out = (float*)d_out;

    float *h_p, *m_p, *agg_p, *gx_p, *gh_p, *pool_p, *cnt_p;
    cudaGetSymbolAddress((void**)&h_p,   g_h);
    cudaGetSymbolAddress((void**)&m_p,   g_m);
    cudaGetSymbolAddress((void**)&agg_p, g_agg);
    cudaGetSymbolAddress((void**)&gx_p,  g_gx);
    cudaGetSymbolAddress((void**)&gh_p,  g_gh);
    cudaGetSymbolAddress((void**)&pool_p, g_pool);
    cudaGetSymbolAddress((void**)&cnt_p,  g_cnt);

    const int embed_smem = (FEAT * H + 32 * FEAT) * 4;  // 57600 B
    cudaFuncSetAttribute(embed_kernel,
                         cudaFuncAttributeMaxDynamicSharedMemorySize, embed_smem);

    // 1) embed
    embed_kernel<<<M_PAD / 32, 128, embed_smem>>>(x, W_emb);

    // 2) message-passing steps
    for (int s = 0; s < STEPS; s++) {
        gemm_f2<false><<<dim3(1, M_PAD / 128), 256>>>(
            h_p, W_msg + (size_t)s * H * H, nullptr, m_p, H);
        cudaMemsetAsync(agg_p, 0, (size_t)M_PAD * H * sizeof(float));
        scatter_kernel<<<(N_EDGES * 32) / 256, 256>>>(ei);
        gemm_f2<true><<<dim3(3, M_PAD / 128), 256>>>(
            agg_p, W_ih, b_ih, gx_p, 3 * H);
        gemm_f2<true><<<dim3(3, M_PAD / 128), 256>>>(
            h_p, W_hh, b_hh, gh_p, 3 * H);
        gru_kernel<<<(M_PAD * 32) / 256, 256>>>();
    }

    // 3) pooling
    cudaMemsetAsync(pool_p, 0, N_GRAPHS * H * sizeof(float));
    cudaMemsetAsync(cnt_p, 0, N_GRAPHS * sizeof(float));
    pool_kernel<<<(N_NODES + 255) / 256, 128>>>(batch);

    // 4) head
    head_kernel<<<N_GRAPHS, H>>>(W1, b1, W2, b2, out);
}

// round 4
// speedup vs baseline: 1.4388x; 1.3493x over previous
#include <cuda_runtime.h>
#include <cuda_bf16.h>
#include <math.h>
#include <stdint.h>

#define N_NODES  50000
#define N_EDGES  800000
#define FEAT     90
#define H        128
#define STEPS    4
#define N_GRAPHS 100
#define M_PAD    50048   // 128 * 391
#define M_TILES  (M_PAD / 128)

typedef unsigned long long u64;

// ---------------- device scratch ----------------
__device__ float g_h  [(size_t)M_PAD * H];
__device__ float g_m  [(size_t)M_PAD * H];
__device__ float g_agg[(size_t)M_PAD * H];
__device__ float g_gx [(size_t)M_PAD * 3 * H];
__device__ float g_gh [(size_t)M_PAD * 3 * H];
__device__ float g_pool[N_GRAPHS * H];
__device__ float g_cnt [N_GRAPHS];

// bf16-split, transposed weights: layout [n][k], k = 0..127
__device__ __nv_bfloat16 g_wmsg_h[STEPS * H * H];
__device__ __nv_bfloat16 g_wmsg_l[STEPS * H * H];
__device__ __nv_bfloat16 g_wih_h[3 * H * H];
__device__ __nv_bfloat16 g_wih_l[3 * H * H];
__device__ __nv_bfloat16 g_whh_h[3 * H * H];
__device__ __nv_bfloat16 g_whh_l[3 * H * H];

// ---------------- PTX helpers ----------------
__device__ __forceinline__ uint32_t smem_u32(const void* p) {
    uint32_t a;
    asm("{ .reg .u64 t; cvta.to.shared.u64 t, %1; cvt.u32.u64 %0, t; }" : "=r"(a) : "l"(p));
    return a;
}

__device__ __forceinline__ void ldsm_x4(uint32_t& r0, uint32_t& r1, uint32_t& r2, uint32_t& r3,
                                        uint32_t addr) {
    asm volatile("ldmatrix.sync.aligned.m8n8.x4.shared.b16 {%0,%1,%2,%3}, [%4];"
                 : "=r"(r0), "=r"(r1), "=r"(r2), "=r"(r3) : "r"(addr));
}

__device__ __forceinline__ void mma_bf16(float* c, const uint32_t* a, const uint32_t* b) {
    asm volatile(
        "mma.sync.aligned.m16n8k16.row.col.f32.bf16.bf16.f32 "
        "{%0,%1,%2,%3}, {%4,%5,%6,%7}, {%8,%9}, {%0,%1,%2,%3};"
        : "+f"(c[0]), "+f"(c[1]), "+f"(c[2]), "+f"(c[3])
        : "r"(a[0]), "r"(a[1]), "r"(a[2]), "r"(a[3]), "r"(b[0]), "r"(b[1]));
}

// swizzled tile offset: row r (0..127), 16B-chunk c (0..15); 256B rows
__device__ __forceinline__ uint32_t swz(int r, int c) {
    return (uint32_t)r * 256 + (uint32_t)((c ^ (r & 7)) << 4);
}

// ---------------- weight prep: split to bf16 hi/lo, transpose to [n][k] -------
__global__ void prep_weights(const float* __restrict__ Wmsg,
                             const float* __restrict__ Wih,
                             const float* __restrict__ Whh) {
    int i = blockIdx.x * 256 + threadIdx.x;
    float v;
    __nv_bfloat16 *ph, *pl;
    if (i < STEPS * H * H) {                       // msg: [s][n][k] <- Wmsg[s][k][n]
        int s = i >> 14, r = i & 16383;
        int n = r >> 7, k = r & 127;
        v = Wmsg[(s << 14) + k * H + n];
        ph = g_wmsg_h + i; pl = g_wmsg_l + i;
    } else if (i < STEPS * H * H + 3 * H * H) {    // ih: [n][k] <- Wih[k][n], n<384
        int j = i - STEPS * H * H;
        int n = j >> 7, k = j & 127;
        v = Wih[k * 384 + n];
        ph = g_wih_h + j; pl = g_wih_l + j;
    } else if (i < STEPS * H * H + 6 * H * H) {
        int j = i - STEPS * H * H - 3 * H * H;
        int n = j >> 7, k = j & 127;
        v = Whh[k * 384 + n];
        ph = g_whh_h + j; pl = g_whh_l + j;
    } else return;
    __nv_bfloat16 hi = __float2bfloat16(v);
    __nv_bfloat16 lo = __float2bfloat16(v - __bfloat162float(hi));
    *ph = hi; *pl = lo;
}

// ---------------- mma.sync GEMM: C[M_PAD,N] = A[M_PAD,128] @ W[128,N] (+bias) --
// bf16x3 emulation: C = Ah*Bh + Ah*Bl + Al*Bh (fp32 accum).
// One CTA per 128 rows; 512 threads = 16 warps, warp tile m32 x n32.
// A fp32 -> split hi/lo in-kernel; B pre-split [n][k].
#define SM_A_H 0
#define SM_A_L 32768
#define SM_B_H 65536
#define SM_B_L 98304
#define SM_BIAS 131072
#define GEMM_SMEM (131072 + 1536)

__global__ void __launch_bounds__(512, 1) gemm_mma(
        const float* __restrict__ A,
        const __nv_bfloat16* __restrict__ Bh, const __nv_bfloat16* __restrict__ Bl,
        const float* __restrict__ bias, float* __restrict__ C, int N) {
    extern __shared__ char smem[];
    const uint32_t sbase = smem_u32(smem);
    const int tid = threadIdx.x;
    const int wid = tid >> 5;
    const int lane = tid & 31;
    const int m0 = blockIdx.x * 128;

    // ---- load A tile (128x128 fp32), split to bf16 hi/lo, swizzled store ----
    {
        const float* Ab = A + (size_t)m0 * 128;
        #pragma unroll
        for (int it = 0; it < 8; it++) {
            int idx = it * 512 + tid;          // 0..4095
            int row = idx >> 5;
            int q = idx & 31;                  // float4 index; k0 = q*4
            float4 v = *(const float4*)(Ab + row * 128 + q * 4);
            __nv_bfloat16 h0 = __float2bfloat16(v.x);
            __nv_bfloat16 h1 = __float2bfloat16(v.y);
            __nv_bfloat16 h2 = __float2bfloat16(v.z);
            __nv_bfloat16 h3 = __float2bfloat16(v.w);
            __nv_bfloat16 l0 = __float2bfloat16(v.x - __bfloat162float(h0));
            __nv_bfloat16 l1 = __float2bfloat16(v.y - __bfloat162float(h1));
            __nv_bfloat16 l2 = __float2bfloat16(v.z - __bfloat162float(h2));
            __nv_bfloat16 l3 = __float2bfloat16(v.w - __bfloat162float(h3));
            uint32_t off = swz(row, q >> 1) + (q & 1) * 8;
            uint2 hw, lw;
            hw.x = (uint32_t)__bfloat16_as_ushort(h0) | ((uint32_t)__bfloat16_as_ushort(h1) << 16);
            hw.y = (uint32_t)__bfloat16_as_ushort(h2) | ((uint32_t)__bfloat16_as_ushort(h3) << 16);
            lw.x = (uint32_t)__bfloat16_as_ushort(l0) | ((uint32_t)__bfloat16_as_ushort(l1) << 16);
            lw.y = (uint32_t)__bfloat16_as_ushort(l2) | ((uint32_t)__bfloat16_as_ushort(l3) << 16);
            *(uint2*)(smem + SM_A_H + off) = hw;
            *(uint2*)(smem + SM_A_L + off) = lw;
        }
    }
    // ---- bias -> smem ----
    if (bias) {
        for (int i = tid; i < N; i += 512)
            *(float*)(smem + SM_BIAS + i * 4) = bias[i];
    }

    const int wm = (wid & 3) * 32;          // warp row offset
    const int wn = (wid >> 2) * 32;         // warp col offset within tile
    const int n_tiles = N >> 7;

    for (int nt = 0; nt < n_tiles; nt++) {
        __syncthreads();   // A ready (nt=0) / previous compute done (nt>0)
        // ---- load B sub-tile 128n x 128k hi+lo, swizzled ----
        {
            const __nv_bfloat16* bh = Bh + (size_t)nt * 128 * 128;
            const __nv_bfloat16* bl = Bl + (size_t)nt * 128 * 128;
            #pragma unroll
            for (int it = 0; it < 4; it++) {
                int idx = it * 512 + tid;       // 0..2047
                int row = idx >> 4;
                int c = idx & 15;
                uint32_t off = swz(row, c);
                *(uint4*)(smem + SM_B_H + off) = *(const uint4*)(bh + row * 128 + c * 8);
                *(uint4*)(smem + SM_B_L + off) = *(const uint4*)(bl + row * 128 + c * 8);
            }
        }
        __syncthreads();

        // ---- compute: 8 k-steps, warp tile m32 x n32 ----
        float acc[2][4][4];
        #pragma unroll
        for (int mi = 0; mi < 2; mi++)
            #pragma unroll
            for (int ni = 0; ni < 4; ni++)
                #pragma unroll
                for (int j = 0; j < 4; j++) acc[mi][ni][j] = 0.f;

        #pragma unroll
        for (int ks = 0; ks < 8; ks++) {
            const int c0 = ks * 2;
            uint32_t ah[2][4], al[2][4], bh[4][2], bl[4][2];
            // A fragments: lanes 0-15 -> chunk c0, rows +lane&15; lanes 16-31 -> chunk c0+1
            {
                int arow = (lane & 15);
                int ac = c0 + (lane >> 4);
                #pragma unroll
                for (int mi = 0; mi < 2; mi++) {
                    uint32_t o = swz(wm + mi * 16 + arow, ac);
                    ldsm_x4(ah[mi][0], ah[mi][1], ah[mi][2], ah[mi][3], sbase + SM_A_H + o);
                    ldsm_x4(al[mi][0], al[mi][1], al[mi][2], al[mi][3], sbase + SM_A_L + o);
                }
            }
            // B fragments: lanes 0-7 n0-7/c0, 8-15 n0-7/c0+1, 16-23 n8-15/c0, 24-31 n8-15/c0+1
            {
                int brow = ((lane >> 4) << 3) + (lane & 7);
                int bc = c0 + ((lane >> 3) & 1);
                #pragma unroll
                for (int nj = 0; nj < 2; nj++) {
                    uint32_t o = swz(wn + nj * 16 + brow, bc);
                    uint32_t t0, t1, t2, t3;
                    ldsm_x4(t0, t1, t2, t3, sbase + SM_B_H + o);
                    bh[nj * 2][0] = t0; bh[nj * 2][1] = t1;
                    bh[nj * 2 + 1][0] = t2; bh[nj * 2 + 1][1] = t3;
                    ldsm_x4(t0, t1, t2, t3, sbase + SM_B_L + o);
                    bl[nj * 2][0] = t0; bl[nj * 2][1] = t1;
                    bl[nj * 2 + 1][0] = t2; bl[nj * 2 + 1][1] = t3;
                }
            }
            #pragma unroll
            for (int mi = 0; mi < 2; mi++)
                #pragma unroll
                for (int ni = 0; ni < 4; ni++) {
                    mma_bf16(acc[mi][ni], ah[mi], bh[ni]);
                    mma_bf16(acc[mi][ni], ah[mi], bl[ni]);
                    mma_bf16(acc[mi][ni], al[mi], bh[ni]);
                }
        }

        // ---- epilogue: store fragments to C (+bias) ----
        {
            const int r0 = m0 + wm + (lane >> 2);
            const int cb = nt * 128 + wn + (lane & 3) * 2;
            #pragma unroll
            for (int mi = 0; mi < 2; mi++) {
                #pragma unroll
                for (int ni = 0; ni < 4; ni++) {
                    int col = cb + ni * 8;
                    float bx = 0.f, by = 0.f;
                    if (bias) {
                        float2 bb = *(const float2*)(smem + SM_BIAS + col * 4);
                        bx = bb.x; by = bb.y;
                    }
                    float* c0p = C + (size_t)(r0 + mi * 16) * N + col;
                    float* c1p = C + (size_t)(r0 + mi * 16 + 8) * N + col;
                    *(float2*)c0p = make_float2(acc[mi][ni][0] + bx, acc[mi][ni][1] + by);
                    *(float2*)c1p = make_float2(acc[mi][ni][2] + bx, acc[mi][ni][3] + by);
                }
            }
        }
    }
}

// ---------------- embedding: h = relu(x @ W_emb), K=90 ----------------
__global__ void embed_kernel(const float* __restrict__ x,
                             const float* __restrict__ Wemb) {
    extern __shared__ float sm[];
    float* Ws = sm;               // FEAT*H
    float* xs = sm + FEAT * H;    // 32*FEAT
    const int tid = threadIdx.x;
    for (int i = tid; i < FEAT * H; i += 128) Ws[i] = Wemb[i];
    const int n0 = blockIdx.x * 32;
    for (int i = tid; i < 32 * FEAT; i += 128) {
        int r = i / FEAT, cc = i - r * FEAT;
        int n = n0 + r;
        xs[i] = (n < N_NODES) ? x[(size_t)n * FEAT + cc] : 0.f;
    }
    __syncthreads();
    const int c = tid;
    for (int r = 0; r < 32; r++) {
        float acc = 0.f;
        const float* xr = xs + r * FEAT;
        #pragma unroll 6
        for (int k = 0; k < FEAT; k++) acc = fmaf(xr[k], Ws[k * H + c], acc);
        g_h[(size_t)(n0 + r) * H + c] = fmaxf(acc, 0.f);
    }
}

// ---------------- edge scatter: agg[dst] += m[src], one warp per edge --------
__global__ void scatter_kernel(const int* __restrict__ ei) {
    const int gw = (blockIdx.x * blockDim.x + threadIdx.x) >> 5;
    const int lane = threadIdx.x & 31;
    const int src = ei[gw];
    const int dst = ei[N_EDGES + gw];
    float4 v = *((const float4*)(g_m + (size_t)src * H) + lane);
    float* p = g_agg + (size_t)dst * H + lane * 4;
    asm volatile("red.global.add.v4.f32 [%0], {%1,%2,%3,%4};"
                 :: "l"(p), "f"(v.x), "f"(v.y), "f"(v.z), "f"(v.w)
                 : "memory");
}

// ---------------- GRU elementwise (float4 vectorized) ------------------------
__device__ __forceinline__ float sigmoidf_(float x) { return 1.f / (1.f + expf(-x)); }

__global__ void gru_kernel() {
    const int v = blockIdx.x * blockDim.x + threadIdx.x;  // vec4 index, < M_PAD*32
    const int node = v >> 5;
    const int c4 = (v & 31) * 4;
    const size_t gb = (size_t)node * 384 + c4;
    const size_t hb = (size_t)node * 128 + c4;
    float4 xr = *(const float4*)&g_gx[gb];
    float4 xz = *(const float4*)&g_gx[gb + 128];
    float4 xn = *(const float4*)&g_gx[gb + 256];
    float4 hr = *(const float4*)&g_gh[gb];
    float4 hz = *(const float4*)&g_gh[gb + 128];
    float4 hn = *(const float4*)&g_gh[gb + 256];
    float4 hv = *(const float4*)&g_h[hb];
    float4 o;
    {
        float r = sigmoidf_(xr.x + hr.x), z = sigmoidf_(xz.x + hz.x);
        float nn = tanhf(xn.x + r * hn.x);
        o.x = (1.f - z) * nn + z * hv.x;
    }
    {
        float r = sigmoidf_(xr.y + hr.y), z = sigmoidf_(xz.y + hz.y);
        float nn = tanhf(xn.y + r * hn.y);
        o.y = (1.f - z) * nn + z * hv.y;
    }
    {
        float r = sigmoidf_(xr.z + hr.z), z = sigmoidf_(xz.z + hz.z);
        float nn = tanhf(xn.z + r * hn.z);
        o.z = (1.f - z) * nn + z * hv.z;
    }
    {
        float r = sigmoidf_(xr.w + hr.w), z = sigmoidf_(xz.w + hz.w);
        float nn = tanhf(xn.w + r * hn.w);
        o.w = (1.f - z) * nn + z * hv.w;
    }
    *(float4*)&g_h[hb] = o;
}

// ---------------- pooling: sum relu(h) per graph (batch sorted) --------------
__global__ void pool_kernel(const int* __restrict__ batch) {
    __shared__ int bs[256];
    const int tid = threadIdx.x;        // 128 threads, one column each
    const int n0 = blockIdx.x * 256;
    const int cnt = min(256, N_NODES - n0);
    for (int i = tid; i < cnt; i += 128) bs[i] = batch[n0 + i];
    __syncthreads();
    const int c = tid;
    float sum = 0.f;
    int cur = bs[0];
    int run = 0;
    for (int i = 0; i < cnt; i++) {
        int b = bs[i];
        if (b != cur) {
            atomicAdd(&g_pool[cur * H + c], sum);
            if (c == 0) atomicAdd(&g_cnt[cur], (float)run);
            sum = 0.f; run = 0; cur = b;
        }
        sum += fmaxf(g_h[(size_t)(n0 + i) * H + c], 0.f);
        run++;
    }
    atomicAdd(&g_pool[cur * H + c], sum);
    if (c == 0) atomicAdd(&g_cnt[cur], (float)run);
}

// ---------------- head: mean -> Linear+ReLU -> Linear -> softplus ------------
__global__ void head_kernel(const float* __restrict__ W1, const float* __restrict__ b1,
                            const float* __restrict__ W2, const float* __restrict__ b2,
                            float* __restrict__ out) {
    __shared__ float ps[H];
    __shared__ float hs[H];
    const int g = blockIdx.x, c = threadIdx.x;
    float cnt = fmaxf(g_cnt[g], 1.f);
    ps[c] = g_pool[g * H + c] / cnt;
    __syncthreads();
    float acc = b1[c];
    #pragma unroll 8
    for (int k = 0; k < H; k++) acc = fmaf(ps[k], W1[k * H + c], acc);
    hs[c] = fmaxf(acc, 0.f) * W2[c];
    __syncthreads();
    for (int s = 64; s > 0; s >>= 1) {
        if (c < s) hs[c] += hs[c + s];
        __syncthreads();
    }
    if (c == 0) {
        float xv = hs[0] + b2[0];
        out[g] = (xv > 0.f) ? (xv + log1pf(expf(-xv))) : log1pf(expf(xv));
    }
}

// ---------------- launch ------------------------------------------------------
extern "C" void kernel_launch(void* const* d_in, const int* in_sizes, int n_in,
                              void* d_out, int out_size) {
    const float* x     = (const float*)d_in[0];
    const int*   ei    = (const int*)d_in[1];
    const int*   batch = (const int*)d_in[2];
    const float* W_emb = (const float*)d_in[3];
    const float* W_msg = (const float*)d_in[4];
    const float* W_ih  = (const float*)d_in[5];
    const float* W_hh  = (const float*)d_in[6];
    const float* b_ih  = (const float*)d_in[7];
    const float* b_hh  = (const float*)d_in[8];
    const float* W1    = (const float*)d_in[9];
    const float* b1    = (const float*)d_in[10];
    const float* W2    = (const float*)d_in[11];
    const float* b2    = (const float*)d_in[12];
    float* out = (float*)d_out;

    float *h_p, *m_p, *agg_p, *gx_p, *gh_p, *pool_p, *cnt_p;
    cudaGetSymbolAddress((void**)&h_p,   g_h);
    cudaGetSymbolAddress((void**)&m_p,   g_m);
    cudaGetSymbolAddress((void**)&agg_p, g_agg);
    cudaGetSymbolAddress((void**)&gx_p,  g_gx);
    cudaGetSymbolAddress((void**)&gh_p,  g_gh);
    cudaGetSymbolAddress((void**)&pool_p, g_pool);
    cudaGetSymbolAddress((void**)&cnt_p,  g_cnt);

    __nv_bfloat16 *wmsg_h, *wmsg_l, *wih_h, *wih_l, *whh_h, *whh_l;
    cudaGetSymbolAddress((void**)&wmsg_h, g_wmsg_h);
    cudaGetSymbolAddress((void**)&wmsg_l, g_wmsg_l);
    cudaGetSymbolAddress((void**)&wih_h,  g_wih_h);
    cudaGetSymbolAddress((void**)&wih_l,  g_wih_l);
    cudaGetSymbolAddress((void**)&whh_h,  g_whh_h);
    cudaGetSymbolAddress((void**)&whh_l,  g_whh_l);

    const int embed_smem = (FEAT * H + 32 * FEAT) * 4;  // 57600 B
    cudaFuncSetAttribute(embed_kernel,
                         cudaFuncAttributeMaxDynamicSharedMemorySize, embed_smem);
    cudaFuncSetAttribute(gemm_mma,
                         cudaFuncAttributeMaxDynamicSharedMemorySize, GEMM_SMEM);

    // 0) weight prep (bf16 split + transpose)
    prep_weights<<<(STEPS * H * H + 6 * H * H + 255) / 256, 256>>>(W_msg, W_ih, W_hh);

    // 1) embed
    embed_kernel<<<M_PAD / 32, 128, embed_smem>>>(x, W_emb);

    // 2) message-passing steps
    for (int s = 0; s < STEPS; s++) {
        gemm_mma<<<M_TILES, 512, GEMM_SMEM>>>(
            h_p, wmsg_h + (size_t)s * H * H, wmsg_l + (size_t)s * H * H,
            nullptr, m_p, H);
        cudaMemsetAsync(agg_p, 0, (size_t)M_PAD * H * sizeof(float));
        scatter_kernel<<<(N_EDGES * 32) / 256, 256>>>(ei);
        gemm_mma<<<M_TILES, 512, GEMM_SMEM>>>(agg_p, wih_h, wih_l, b_ih, gx_p, 3 * H);
        gemm_mma<<<M_TILES, 512, GEMM_SMEM>>>(h_p,   whh_h, whh_l, b_hh, gh_p, 3 * H);
        gru_kernel<<<(M_PAD * 32) / 256, 256>>>();
    }

    // 3) pooling
    cudaMemsetAsync(pool_p, 0, N_GRAPHS * H * sizeof(float));
    cudaMemsetAsync(cnt_p, 0, N_GRAPHS * sizeof(float));
    pool_kernel<<<(N_NODES + 255) / 256, 128>>>(batch);

    // 4) head
    head_kernel<<<N_GRAPHS, H>>>(W1, b1, W2, b2, out);
}

// round 5
// speedup vs baseline: 1.8242x; 1.2678x over previous
#include <cuda_runtime.h>
#include <cuda_bf16.h>
#include <math.h>
#include <stdint.h>

#define N_NODES  50000
#define N_EDGES  800000
#define FEAT     90
#define H        128
#define STEPS    4
#define N_GRAPHS 100
#define M_PAD    50048   // 128 * 391
#define M_TILES  (M_PAD / 128)

typedef unsigned long long u64;

// ---------------- device scratch ----------------
__device__ float g_h  [(size_t)M_PAD * H];
__device__ float g_agg[(size_t)M_PAD * H];
__device__ float g_gx [(size_t)M_PAD * 3 * H];
__device__ float g_gh [(size_t)M_PAD * 3 * H];
__device__ float g_pool[N_GRAPHS * H];
__device__ float g_cnt [N_GRAPHS];

// CSR for gather aggregation
__device__ int g_deg[N_NODES];
__device__ int g_off[N_NODES + 1];
__device__ int g_cur[N_NODES];
__device__ int g_eid[N_EDGES];

// bf16-split, transposed weights, layout [n][k]
__device__ __nv_bfloat16 g_wcomb_h[STEPS * 3 * H * H];  // W_msg[s] @ W_ih, [s][n][k]
__device__ __nv_bfloat16 g_wcomb_l[STEPS * 3 * H * H];
__device__ __nv_bfloat16 g_whh_h[3 * H * H];
__device__ __nv_bfloat16 g_whh_l[3 * H * H];

// ---------------- PTX helpers ----------------
__device__ __forceinline__ uint32_t smem_u32(const void* p) {
    uint32_t a;
    asm("{ .reg .u64 t; cvta.to.shared.u64 t, %1; cvt.u32.u64 %0, t; }" : "=r"(a) : "l"(p));
    return a;
}

__device__ __forceinline__ void ldsm_x4(uint32_t& r0, uint32_t& r1, uint32_t& r2, uint32_t& r3,
                                        uint32_t addr) {
    asm volatile("ldmatrix.sync.aligned.m8n8.x4.shared.b16 {%0,%1,%2,%3}, [%4];"
                 : "=r"(r0), "=r"(r1), "=r"(r2), "=r"(r3) : "r"(addr));
}

__device__ __forceinline__ void mma_bf16(float* c, const uint32_t* a, const uint32_t* b) {
    asm volatile(
        "mma.sync.aligned.m16n8k16.row.col.f32.bf16.bf16.f32 "
        "{%0,%1,%2,%3}, {%4,%5,%6,%7}, {%8,%9}, {%0,%1,%2,%3};"
        : "+f"(c[0]), "+f"(c[1]), "+f"(c[2]), "+f"(c[3])
        : "r"(a[0]), "r"(a[1]), "r"(a[2]), "r"(a[3]), "r"(b[0]), "r"(b[1]));
}

// swizzled tile offset: row r (0..127), 16B-chunk c (0..15); 256B rows
__device__ __forceinline__ uint32_t swz(int r, int c) {
    return (uint32_t)r * 256 + (uint32_t)((c ^ (r & 7)) << 4);
}

// ---------------- CSR build ----------------
__global__ void hist_kernel(const int* __restrict__ ei) {
    int e = blockIdx.x * 256 + threadIdx.x;
    if (e < N_EDGES) atomicAdd(&g_deg[ei[N_EDGES + e]], 1);
}

__global__ void scan_kernel() {   // single block, 1024 threads
    const int tid = threadIdx.x, lane = tid & 31, w = tid >> 5;
    __shared__ int wsum[32];
    int total = 0;
    for (int base = 0; base < N_NODES; base += 1024) {
        int i = base + tid;
        int v = (i < N_NODES) ? g_deg[i] : 0;
        int x = v;
        #pragma unroll
        for (int d = 1; d < 32; d <<= 1) {
            int t = __shfl_up_sync(0xFFFFFFFFu, x, d);
            if (lane >= d) x += t;
        }
        if (lane == 31) wsum[w] = x;
        __syncthreads();
        if (w == 0) {
            int y = wsum[lane];
            #pragma unroll
            for (int d = 1; d < 32; d <<= 1) {
                int t = __shfl_up_sync(0xFFFFFFFFu, y, d);
                if (lane >= d) y += t;
            }
            wsum[lane] = y;
        }
        __syncthreads();
        int woff = (w == 0) ? 0 : wsum[w - 1];
        int excl = total + woff + x - v;
        if (i < N_NODES) { g_off[i] = excl; g_cur[i] = excl; }
        int chunk = wsum[31];
        __syncthreads();
        total += chunk;
    }
    if (tid == 0) g_off[N_NODES] = total;
}

__global__ void fill_kernel(const int* __restrict__ ei) {
    int e = blockIdx.x * 256 + threadIdx.x;
    if (e < N_EDGES) {
        int dst = ei[N_EDGES + e];
        int pos = atomicAdd(&g_cur[dst], 1);
        g_eid[pos] = ei[e];
    }
}

// ---------------- gather: agg[n] = sum_{e: dst=n} h[src[e]] ----------------
__global__ void gather_kernel() {
    const int node = (blockIdx.x * blockDim.x + threadIdx.x) >> 5;
    if (node >= N_NODES) return;
    const int lane = threadIdx.x & 31;
    const int beg = g_off[node], end = g_off[node + 1];
    float4 acc = make_float4(0.f, 0.f, 0.f, 0.f);
    #pragma unroll 4
    for (int e = beg; e < end; e++) {
        int src = __ldg(&g_eid[e]);
        float4 v = *(const float4*)(g_h + (size_t)src * H + lane * 4);
        acc.x += v.x; acc.y += v.y; acc.z += v.z; acc.w += v.w;
    }
    *(float4*)(g_agg + (size_t)node * H + lane * 4) = acc;
}

// ---------------- weight prep ----------------
// W_hh: split to bf16 hi/lo, transpose to [n][k]
__global__ void prep_whh(const float* __restrict__ Whh) {
    int j = blockIdx.x * 256 + threadIdx.x;
    if (j >= 3 * H * H) return;
    int n = j >> 7, k = j & 127;
    float v = Whh[k * 384 + n];
    __nv_bfloat16 hi = __float2bfloat16(v);
    __nv_bfloat16 lo = __float2bfloat16(v - __bfloat162float(hi));
    g_whh_h[j] = hi; g_whh_l[j] = lo;
}

// W_comb[s] = W_msg[s] @ W_ih  (fp32), split hi/lo, layout [s][n][k]
__global__ void prep_wcomb(const float* __restrict__ Wmsg,
                           const float* __restrict__ Wih) {
    int i = blockIdx.x * 256 + threadIdx.x;
    if (i >= STEPS * 3 * H * H) return;
    int s = i / (3 * H * H);
    int r = i % (3 * H * H);
    int k = r / 384;       // lanes share k -> Wih coalesced, Wmsg broadcast
    int n = r % 384;
    const float* wm = Wmsg + (s << 14) + k * H;
    float acc = 0.f;
    #pragma unroll 8
    for (int j = 0; j < H; j++) acc = fmaf(wm[j], Wih[j * 384 + n], acc);
    __nv_bfloat16 hi = __float2bfloat16(acc);
    __nv_bfloat16 lo = __float2bfloat16(acc - __bfloat162float(hi));
    size_t o = (size_t)s * 3 * H * H + (size_t)n * H + k;
    g_wcomb_h[o] = hi; g_wcomb_l[o] = lo;
}

// ---------------- mma.sync GEMM: C[M_PAD,N] = A[M_PAD,128] @ W[128,N] (+bias) --
// bf16x3: C = Ah*Bh + Ah*Bl + Al*Bh (fp32 accum). 512 thr, warp tile m32 x n32.
#define SM_A_H 0
#define SM_A_L 32768
#define SM_B_H 65536
#define SM_B_L 98304
#define SM_BIAS 131072
#define GEMM_SMEM (131072 + 1536)

__global__ void __launch_bounds__(512, 1) gemm_mma(
        const float* __restrict__ A,
        const __nv_bfloat16* __restrict__ Bh, const __nv_bfloat16* __restrict__ Bl,
        const float* __restrict__ bias, float* __restrict__ C, int N) {
    extern __shared__ char smem[];
    const uint32_t sbase = smem_u32(smem);
    const int tid = threadIdx.x;
    const int wid = tid >> 5;
    const int lane = tid & 31;
    const int m0 = blockIdx.x * 128;

    // ---- load A tile (128x128 fp32), split to bf16 hi/lo, swizzled store ----
    {
        const float* Ab = A + (size_t)m0 * 128;
        #pragma unroll
        for (int it = 0; it < 8; it++) {
            int idx = it * 512 + tid;          // 0..4095
            int row = idx >> 5;
            int q = idx & 31;                  // float4 index; k0 = q*4
            float4 v = *(const float4*)(Ab + row * 128 + q * 4);
            __nv_bfloat16 h0 = __float2bfloat16(v.x);
            __nv_bfloat16 h1 = __float2bfloat16(v.y);
            __nv_bfloat16 h2 = __float2bfloat16(v.z);
            __nv_bfloat16 h3 = __float2bfloat16(v.w);
            __nv_bfloat16 l0 = __float2bfloat16(v.x - __bfloat162float(h0));
            __nv_bfloat16 l1 = __float2bfloat16(v.y - __bfloat162float(h1));
            __nv_bfloat16 l2 = __float2bfloat16(v.z - __bfloat162float(h2));
            __nv_bfloat16 l3 = __float2bfloat16(v.w - __bfloat162float(h3));
            uint32_t off = swz(row, q >> 1) + (q & 1) * 8;
            uint2 hw, lw;
            hw.x = (uint32_t)__bfloat16_as_ushort(h0) | ((uint32_t)__bfloat16_as_ushort(h1) << 16);
            hw.y = (uint32_t)__bfloat16_as_ushort(h2) | ((uint32_t)__bfloat16_as_ushort(h3) << 16);
            lw.x = (uint32_t)__bfloat16_as_ushort(l0) | ((uint32_t)__bfloat16_as_ushort(l1) << 16);
            lw.y = (uint32_t)__bfloat16_as_ushort(l2) | ((uint32_t)__bfloat16_as_ushort(l3) << 16);
            *(uint2*)(smem + SM_A_H + off) = hw;
            *(uint2*)(smem + SM_A_L + off) = lw;
        }
    }
    // ---- bias -> smem ----
    if (bias) {
        for (int i = tid; i < N; i += 512)
            *(float*)(smem + SM_BIAS + i * 4) = bias[i];
    }

    const int wm = (wid & 3) * 32;          // warp row offset
    const int wn = (wid >> 2) * 32;         // warp col offset within tile
    const int n_tiles = N >> 7;

    for (int nt = 0; nt < n_tiles; nt++) {
        __syncthreads();
        // ---- load B sub-tile 128n x 128k hi+lo, swizzled ----
        {
            const __nv_bfloat16* bh = Bh + (size_t)nt * 128 * 128;
            const __nv_bfloat16* bl = Bl + (size_t)nt * 128 * 128;
            #pragma unroll
            for (int it = 0; it < 4; it++) {
                int idx = it * 512 + tid;       // 0..2047
                int row = idx >> 4;
                int c = idx & 15;
                uint32_t off = swz(row, c);
                *(uint4*)(smem + SM_B_H + off) = *(const uint4*)(bh + row * 128 + c * 8);
                *(uint4*)(smem + SM_B_L + off) = *(const uint4*)(bl + row * 128 + c * 8);
            }
        }
        __syncthreads();

        // ---- compute: 8 k-steps, warp tile m32 x n32 ----
        float acc[2][4][4];
        #pragma unroll
        for (int mi = 0; mi < 2; mi++)
            #pragma unroll
            for (int ni = 0; ni < 4; ni++)
                #pragma unroll
                for (int j = 0; j < 4; j++) acc[mi][ni][j] = 0.f;

        #pragma unroll
        for (int ks = 0; ks < 8; ks++) {
            const int c0 = ks * 2;
            uint32_t ah[2][4], al[2][4], bh[4][2], bl[4][2];
            {
                int arow = (lane & 15);
                int ac = c0 + (lane >> 4);
                #pragma unroll
                for (int mi = 0; mi < 2; mi++) {
                    uint32_t o = swz(wm + mi * 16 + arow, ac);
                    ldsm_x4(ah[mi][0], ah[mi][1], ah[mi][2], ah[mi][3], sbase + SM_A_H + o);
                    ldsm_x4(al[mi][0], al[mi][1], al[mi][2], al[mi][3], sbase + SM_A_L + o);
                }
            }
            {
                int brow = ((lane >> 4) << 3) + (lane & 7);
                int bc = c0 + ((lane >> 3) & 1);
                #pragma unroll
                for (int nj = 0; nj < 2; nj++) {
                    uint32_t o = swz(wn + nj * 16 + brow, bc);
                    uint32_t t0, t1, t2, t3;
                    ldsm_x4(t0, t1, t2, t3, sbase + SM_B_H + o);
                    bh[nj * 2][0] = t0; bh[nj * 2][1] = t1;
                    bh[nj * 2 + 1][0] = t2; bh[nj * 2 + 1][1] = t3;
                    ldsm_x4(t0, t1, t2, t3, sbase + SM_B_L + o);
                    bl[nj * 2][0] = t0; bl[nj * 2][1] = t1;
                    bl[nj * 2 + 1][0] = t2; bl[nj * 2 + 1][1] = t3;
                }
            }
            #pragma unroll
            for (int mi = 0; mi < 2; mi++)
                #pragma unroll
                for (int ni = 0; ni < 4; ni++) {
                    mma_bf16(acc[mi][ni], ah[mi], bh[ni]);
                    mma_bf16(acc[mi][ni], ah[mi], bl[ni]);
                    mma_bf16(acc[mi][ni], al[mi], bh[ni]);
                }
        }

        // ---- epilogue ----
        {
            const int r0 = m0 + wm + (lane >> 2);
            const int cb = nt * 128 + wn + (lane & 3) * 2;
            #pragma unroll
            for (int mi = 0; mi < 2; mi++) {
                #pragma unroll
                for (int ni = 0; ni < 4; ni++) {
                    int col = cb + ni * 8;
                    float bx = 0.f, by = 0.f;
                    if (bias) {
                        float2 bb = *(const float2*)(smem + SM_BIAS + col * 4);
                        bx = bb.x; by = bb.y;
                    }
                    float* c0p = C + (size_t)(r0 + mi * 16) * N + col;
                    float* c1p = C + (size_t)(r0 + mi * 16 + 8) * N + col;
                    *(float2*)c0p = make_float2(acc[mi][ni][0] + bx, acc[mi][ni][1] + by);
                    *(float2*)c1p = make_float2(acc[mi][ni][2] + bx, acc[mi][ni][3] + by);
                }
            }
        }
    }
}

// ---------------- embedding: h = relu(x @ W_emb), K=90 ----------------
__global__ void embed_kernel(const float* __restrict__ x,
                             const float* __restrict__ Wemb) {
    extern __shared__ float sm[];
    float* Ws = sm;               // FEAT*H
    float* xs = sm + FEAT * H;    // 32*FEAT
    const int tid = threadIdx.x;
    for (int i = tid; i < FEAT * H; i += 128) Ws[i] = Wemb[i];
    const int n0 = blockIdx.x * 32;
    for (int i = tid; i < 32 * FEAT; i += 128) {
        int r = i / FEAT, cc = i - r * FEAT;
        int n = n0 + r;
        xs[i] = (n < N_NODES) ? x[(size_t)n * FEAT + cc] : 0.f;
    }
    __syncthreads();
    const int c = tid;
    for (int r = 0; r < 32; r++) {
        float acc = 0.f;
        const float* xr = xs + r * FEAT;
        #pragma unroll 6
        for (int k = 0; k < FEAT; k++) acc = fmaf(xr[k], Ws[k * H + c], acc);
        g_h[(size_t)(n0 + r) * H + c] = fmaxf(acc, 0.f);
    }
}

// ---------------- GRU elementwise (float4 vectorized) ------------------------
__device__ __forceinline__ float sigmoidf_(float x) { return 1.f / (1.f + expf(-x)); }

__global__ void gru_kernel() {
    const int v = blockIdx.x * blockDim.x + threadIdx.x;  // vec4 index, < M_PAD*32
    const int node = v >> 5;
    const int c4 = (v & 31) * 4;
    const size_t gb = (size_t)node * 384 + c4;
    const size_t hb = (size_t)node * 128 + c4;
    float4 xr = *(const float4*)&g_gx[gb];
    float4 xz = *(const float4*)&g_gx[gb + 128];
    float4 xn = *(const float4*)&g_gx[gb + 256];
    float4 hr = *(const float4*)&g_gh[gb];
    float4 hz = *(const float4*)&g_gh[gb + 128];
    float4 hn = *(const float4*)&g_gh[gb + 256];
    float4 hv = *(const float4*)&g_h[hb];
    float4 o;
    {
        float r = sigmoidf_(xr.x + hr.x), z = sigmoidf_(xz.x + hz.x);
        float nn = tanhf(xn.x + r * hn.x);
        o.x = (1.f - z) * nn + z * hv.x;
    }
    {
        float r = sigmoidf_(xr.y + hr.y), z = sigmoidf_(xz.y + hz.y);
        float nn = tanhf(xn.y + r * hn.y);
        o.y = (1.f - z) * nn + z * hv.y;
    }
    {
        float r = sigmoidf_(xr.z + hr.z), z = sigmoidf_(xz.z + hz.z);
        float nn = tanhf(xn.z + r * hn.z);
        o.z = (1.f - z) * nn + z * hv.z;
    }
    {
        float r = sigmoidf_(xr.w + hr.w), z = sigmoidf_(xz.w + hz.w);
        float nn = tanhf(xn.w + r * hn.w);
        o.w = (1.f - z) * nn + z * hv.w;
    }
    *(float4*)&g_h[hb] = o;
}

// ---------------- pooling: sum relu(h) per graph (batch sorted) --------------
__global__ void pool_kernel(const int* __restrict__ batch) {
    __shared__ int bs[256];
    const int tid = threadIdx.x;        // 128 threads, one column each
    const int n0 = blockIdx.x * 256;
    const int cnt = min(256, N_NODES - n0);
    for (int i = tid; i < cnt; i += 128) bs[i] = batch[n0 + i];
    __syncthreads();
    const int c = tid;
    float sum = 0.f;
    int cur = bs[0];
    int run = 0;
    for (int i = 0; i < cnt; i++) {
        int b = bs[i];
        if (b != cur) {
            atomicAdd(&g_pool[cur * H + c], sum);
            if (c == 0) atomicAdd(&g_cnt[cur], (float)run);
            sum = 0.f; run = 0; cur = b;
        }
        sum += fmaxf(g_h[(size_t)(n0 + i) * H + c], 0.f);
        run++;
    }
    atomicAdd(&g_pool[cur * H + c], sum);
    if (c == 0) atomicAdd(&g_cnt[cur], (float)run);
}

// ---------------- head: mean -> Linear+ReLU -> Linear -> softplus ------------
__global__ void head_kernel(const float* __restrict__ W1, const float* __restrict__ b1,
                            const float* __restrict__ W2, const float* __restrict__ b2,
                            float* __restrict__ out) {
    __shared__ float ps[H];
    __shared__ float hs[H];
    const int g = blockIdx.x, c = threadIdx.x;
    float cnt = fmaxf(g_cnt[g], 1.f);
    ps[c] = g_pool[g * H + c] / cnt;
    __syncthreads();
    float acc = b1[c];
    #pragma unroll 8
    for (int k = 0; k < H; k++) acc = fmaf(ps[k], W1[k * H + c], acc);
    hs[c] = fmaxf(acc, 0.f) * W2[c];
    __syncthreads();
    for (int s = 64; s > 0; s >>= 1) {
        if (c < s) hs[c] += hs[c + s];
        __syncthreads();
    }
    if (c == 0) {
        float xv = hs[0] + b2[0];
        out[g] = (xv > 0.f) ? (xv + log1pf(expf(-xv))) : log1pf(expf(xv));
    }
}

// ---------------- launch ------------------------------------------------------
extern "C" void kernel_launch(void* const* d_in, const int* in_sizes, int n_in,
                              void* d_out, int out_size) {
    const float* x     = (const float*)d_in[0];
    const int*   ei    = (const int*)d_in[1];
    const int*   batch = (const int*)d_in[2];
    const float* W_emb = (const float*)d_in[3];
    const float* W_msg = (const float*)d_in[4];
    const float* W_ih  = (const float*)d_in[5];
    const float* W_hh  = (const float*)d_in[6];
    const float* b_ih  = (const float*)d_in[7];
    const float* b_hh  = (const float*)d_in[8];
    const float* W1    = (const float*)d_in[9];
    const float* b1    = (const float*)d_in[10];
    const float* W2    = (const float*)d_in[11];
    const float* b2    = (const float*)d_in[12];
    float* out = (float*)d_out;

    float *h_p, *agg_p, *gx_p, *gh_p, *pool_p, *cnt_p;
    int* deg_p;
    cudaGetSymbolAddress((void**)&h_p,   g_h);
    cudaGetSymbolAddress((void**)&agg_p, g_agg);
    cudaGetSymbolAddress((void**)&gx_p,  g_gx);
    cudaGetSymbolAddress((void**)&gh_p,  g_gh);
    cudaGetSymbolAddress((void**)&pool_p, g_pool);
    cudaGetSymbolAddress((void**)&cnt_p,  g_cnt);
    cudaGetSymbolAddress((void**)&deg_p,  g_deg);

    __nv_bfloat16 *wcomb_h, *wcomb_l, *whh_h, *whh_l;
    cudaGetSymbolAddress((void**)&wcomb_h, g_wcomb_h);
    cudaGetSymbolAddress((void**)&wcomb_l, g_wcomb_l);
    cudaGetSymbolAddress((void**)&whh_h,   g_whh_h);
    cudaGetSymbolAddress((void**)&whh_l,   g_whh_l);

    const int embed_smem = (FEAT * H + 32 * FEAT) * 4;  // 57600 B
    cudaFuncSetAttribute(embed_kernel,
                         cudaFuncAttributeMaxDynamicSharedMemorySize, embed_smem);
    cudaFuncSetAttribute(gemm_mma,
                         cudaFuncAttributeMaxDynamicSharedMemorySize, GEMM_SMEM);

    // 0) CSR build + weight prep
    cudaMemsetAsync(deg_p, 0, N_NODES * sizeof(int));
    hist_kernel<<<(N_EDGES + 255) / 256, 256>>>(ei);
    scan_kernel<<<1, 1024>>>();
    fill_kernel<<<(N_EDGES + 255) / 256, 256>>>(ei);
    prep_whh<<<(3 * H * H + 255) / 256, 256>>>(W_hh);
    prep_wcomb<<<(STEPS * 3 * H * H + 255) / 256, 256>>>(W_msg, W_ih);

    // 1) embed
    embed_kernel<<<M_PAD / 32, 128, embed_smem>>>(x, W_emb);

    // 2) message-passing steps
    for (int s = 0; s < STEPS; s++) {
        gather_kernel<<<(N_NODES * 32) / 256, 256>>>();
        gemm_mma<<<M_TILES, 512, GEMM_SMEM>>>(
            agg_p, wcomb_h + (size_t)s * 3 * H * H, wcomb_l + (size_t)s * 3 * H * H,
            b_ih, gx_p, 3 * H);
        gemm_mma<<<M_TILES, 512, GEMM_SMEM>>>(h_p, whh_h, whh_l, b_hh, gh_p, 3 * H);
        gru_kernel<<<(M_PAD * 32) / 256, 256>>>();
    }

    // 3) pooling
    cudaMemsetAsync(pool_p, 0, N_GRAPHS * H * sizeof(float));
    cudaMemsetAsync(cnt_p, 0, N_GRAPHS * sizeof(float));
    pool_kernel<<<(N_NODES + 255) / 256, 128>>>(batch);

    // 4) head
    head_kernel<<<N_GRAPHS, H>>>(W1, b1, W2, b2, out);
}